// round 6
// baseline (speedup 1.0000x reference)
#include <cuda_runtime.h>
#include <cuda_bf16.h>
#include <math.h>
#include <stdint.h>

#define BSZn   2
#define SEQn   512
#define DMODEL 768
#define DINNER 1536
#define NHEADSn 24
#define HEADDIMn 64
#define DSTATEn 64
#define CONVDIM 1664
#define DIP    3224
#define BT     (BSZn*SEQn)   // 1024
#define DFF    3072
#define EPSV   1e-5f

// ---------------- scratch ----------------
__device__ float g_xn  [BT*DMODEL];
__device__ float g_zx  [BT*DIP];
__device__ float g_xbcf[BT*CONVDIM];
__device__ float g_xbcb[BT*CONVDIM];
__device__ float g_dtp [BT*NHEADSn];
__device__ float g_dAe [BT*NHEADSn];
__device__ float g_yf  [BT*DINNER];
__device__ float g_yb  [BT*DINNER];
__device__ float g_ysum[BT*DINNER];
__device__ float g_mi  [BT*DMODEL];
__device__ float g_m   [BT*DMODEL];
__device__ float g_h1  [BT*DFF];

// ---------------- helpers ----------------
__device__ __forceinline__ float warp_sum(float v) {
    #pragma unroll
    for (int o = 16; o > 0; o >>= 1) v += __shfl_xor_sync(0xffffffffu, v, o);
    return v;
}
__device__ __forceinline__ float siluf(float x) { return x / (1.f + expf(-x)); }
__device__ __forceinline__ float geluf(float x) { return 0.5f * x * (1.f + erff(x * 0.70710678118654752f)); }

__device__ __forceinline__ uint32_t smem_u32(const void* p) {
    uint32_t a;
    asm("{ .reg .u64 t; cvta.to.shared.u64 t, %1; cvt.u32.u64 %0, t; }" : "=r"(a) : "l"(p));
    return a;
}
__device__ __forceinline__ void mma_bf16(float* c, const uint32_t* a, const uint32_t* b) {
    asm volatile(
        "mma.sync.aligned.m16n8k16.row.col.f32.bf16.bf16.f32 "
        "{%0,%1,%2,%3},{%4,%5,%6,%7},{%8,%9},{%0,%1,%2,%3};"
        : "+f"(c[0]), "+f"(c[1]), "+f"(c[2]), "+f"(c[3])
        : "r"(a[0]), "r"(a[1]), "r"(a[2]), "r"(a[3]), "r"(b[0]), "r"(b[1]));
}
__device__ __forceinline__ void ldsm4(uint32_t* r, uint32_t addr) {
    asm volatile("ldmatrix.sync.aligned.m8n8.x4.shared.b16 {%0,%1,%2,%3}, [%4];"
                 : "=r"(r[0]), "=r"(r[1]), "=r"(r[2]), "=r"(r[3]) : "r"(addr));
}
// split 8 floats -> 4x bf16x2 hi + 4x bf16x2 lo (16B each)
__device__ __forceinline__ void split8(const float4& a, const float4& b, uint4& h4, uint4& l4) {
    float v[8] = {a.x, a.y, a.z, a.w, b.x, b.y, b.z, b.w};
    uint32_t hh[4], ll[4];
    #pragma unroll
    for (int j = 0; j < 4; j++) {
        __nv_bfloat16 h0 = __float2bfloat16_rn(v[2*j]);
        __nv_bfloat16 h1 = __float2bfloat16_rn(v[2*j+1]);
        float l0 = v[2*j]   - __bfloat162float(h0);
        float l1 = v[2*j+1] - __bfloat162float(h1);
        __nv_bfloat162 hv; hv.x = h0; hv.y = h1;
        __nv_bfloat162 lv; lv.x = __float2bfloat16_rn(l0); lv.y = __float2bfloat16_rn(l1);
        hh[j] = *reinterpret_cast<uint32_t*>(&hv);
        ll[j] = *reinterpret_cast<uint32_t*>(&lv);
    }
    h4 = make_uint4(hh[0], hh[1], hh[2], hh[3]);
    l4 = make_uint4(ll[0], ll[1], ll[2], ll[3]);
}

// ---------------- LayerNorm ----------------
__global__ void ln_kernel(const float* __restrict__ in, const float* __restrict__ w,
                          const float* __restrict__ b, float* __restrict__ out) {
    int row = blockIdx.x;
    int tid = threadIdx.x;
    const float* x = in + (long)row * DMODEL;
    float v[3], s = 0.f, ss = 0.f;
    #pragma unroll
    for (int i = 0; i < 3; i++) {
        v[i] = x[tid + i * 256];
        s += v[i]; ss += v[i] * v[i];
    }
    __shared__ float sr[8], sr2[8], bres[2];
    float ws = warp_sum(s), ws2 = warp_sum(ss);
    int lane = tid & 31, wid = tid >> 5;
    if (lane == 0) { sr[wid] = ws; sr2[wid] = ws2; }
    __syncthreads();
    if (tid == 0) {
        float a = 0.f, c = 0.f;
        #pragma unroll
        for (int i = 0; i < 8; i++) { a += sr[i]; c += sr2[i]; }
        bres[0] = a; bres[1] = c;
    }
    __syncthreads();
    float mu  = bres[0] * (1.f / DMODEL);
    float var = bres[1] * (1.f / DMODEL) - mu * mu;
    float r = rsqrtf(var + EPSV);
    #pragma unroll
    for (int i = 0; i < 3; i++) {
        int c = tid + i * 256;
        out[(long)row * DMODEL + c] = (v[i] - mu) * r * w[c] + b[c];
    }
}

// ======= HMMA GEMM (bf16 hi/lo 3-product, ldmatrix): C[M,N] = A @ W^T ========
// CTA tile 128x128, BK=32, 256 thr (8 warps = 4M x 2N), warp tile 32x64.
// smem: bf16 planes Ah/Al/Bh/Bl, 80B row stride (conflict-free LDSM+STS),
// double-buffered, ONE sync per K-iter. EPI: 0=none, 1=gelu+bias, 2=bias+resid
#define RS 80
#define PLANEB (128 * RS)        // 10240
#define BUFB   (4 * PLANEB)      // 40960
#define GEMM_SMEM (2 * BUFB)     // 81920

template<int EPI>
__global__ void __launch_bounds__(256) gemm_mma(
        const float* __restrict__ A, const float* __restrict__ W,
        const float* __restrict__ bias, const float* __restrict__ resid,
        float* __restrict__ C, int M, int N, int K) {
    extern __shared__ char smem[];
    uint32_t sb = smem_u32(smem);
    const int tid = threadIdx.x;
    const int lane = tid & 31, wid = tid >> 5;
    const int warpM = wid & 3;      // 0..3 (32 rows each)
    const int warpN = wid >> 2;     // 0..1 (64 cols each)
    const int row0 = blockIdx.y * 128;
    const int col0 = blockIdx.x * 128;
    const int quad = lane >> 3, r8 = lane & 7;
    const int g = lane >> 2, tg = lane & 3;

    float acc[2][8][4];
    #pragma unroll
    for (int mt = 0; mt < 2; mt++)
        #pragma unroll
        for (int nt = 0; nt < 8; nt++)
            #pragma unroll
            for (int i = 0; i < 4; i++) acc[mt][nt][i] = 0.f;

    const int lrow = tid & 127;     // 0..127
    const int kh   = tid >> 7;      // 0/1 (16-float half of BK)

    // gmem prefetch regs (16 floats A, 16 floats B per thread)
    float4 pa[4], pb[4];
    {
        const float* ap = &A[(long)(row0 + lrow) * K + kh * 16];
        pa[0] = reinterpret_cast<const float4*>(ap)[0];
        pa[1] = reinterpret_cast<const float4*>(ap)[1];
        pa[2] = reinterpret_cast<const float4*>(ap)[2];
        pa[3] = reinterpret_cast<const float4*>(ap)[3];
        int n = col0 + lrow;
        pb[0] = pb[1] = pb[2] = pb[3] = make_float4(0.f, 0.f, 0.f, 0.f);
        if (n < N) {
            const float* bp = &W[(long)n * K + kh * 16];
            pb[0] = reinterpret_cast<const float4*>(bp)[0];
            pb[1] = reinterpret_cast<const float4*>(bp)[1];
            pb[2] = reinterpret_cast<const float4*>(bp)[2];
            pb[3] = reinterpret_cast<const float4*>(bp)[3];
        }
    }

    const int ntiles = K / 32;
    int buf = 0;
    for (int kt = 0; kt < ntiles; kt++) {
        // ---- convert + store current tile into smem[buf] ----
        {
            char* bo = smem + buf * BUFB;
            uint32_t co = (uint32_t)(lrow * RS + kh * 32);  // chunk kg=kh*2 at +0, kg+1 at +16
            uint4 h4, l4;
            split8(pa[0], pa[1], h4, l4);
            *reinterpret_cast<uint4*>(bo + 0 * PLANEB + co)      = h4;
            *reinterpret_cast<uint4*>(bo + 1 * PLANEB + co)      = l4;
            split8(pa[2], pa[3], h4, l4);
            *reinterpret_cast<uint4*>(bo + 0 * PLANEB + co + 16) = h4;
            *reinterpret_cast<uint4*>(bo + 1 * PLANEB + co + 16) = l4;
            split8(pb[0], pb[1], h4, l4);
            *reinterpret_cast<uint4*>(bo + 2 * PLANEB + co)      = h4;
            *reinterpret_cast<uint4*>(bo + 3 * PLANEB + co)      = l4;
            split8(pb[2], pb[3], h4, l4);
            *reinterpret_cast<uint4*>(bo + 2 * PLANEB + co + 16) = h4;
            *reinterpret_cast<uint4*>(bo + 3 * PLANEB + co + 16) = l4;
        }
        __syncthreads();

        // ---- prefetch next tile from gmem ----
        if (kt + 1 < ntiles) {
            int k0 = (kt + 1) * 32;
            const float* ap = &A[(long)(row0 + lrow) * K + k0 + kh * 16];
            pa[0] = reinterpret_cast<const float4*>(ap)[0];
            pa[1] = reinterpret_cast<const float4*>(ap)[1];
            pa[2] = reinterpret_cast<const float4*>(ap)[2];
            pa[3] = reinterpret_cast<const float4*>(ap)[3];
            int n = col0 + lrow;
            pb[0] = pb[1] = pb[2] = pb[3] = make_float4(0.f, 0.f, 0.f, 0.f);
            if (n < N) {
                const float* bp = &W[(long)n * K + k0 + kh * 16];
                pb[0] = reinterpret_cast<const float4*>(bp)[0];
                pb[1] = reinterpret_cast<const float4*>(bp)[1];
                pb[2] = reinterpret_cast<const float4*>(bp)[2];
                pb[3] = reinterpret_cast<const float4*>(bp)[3];
            }
        }

        // ---- compute on smem[buf] ----
        {
            uint32_t pAh = sb + buf * BUFB;
            uint32_t pAl = pAh + PLANEB;
            uint32_t pBh = pAh + 2 * PLANEB;
            uint32_t pBl = pAh + 3 * PLANEB;
            #pragma unroll
            for (int slab = 0; slab < 2; slab++) {
                uint32_t kbA = slab * 32 + (quad >> 1) * 16;
                uint32_t kbB = slab * 32 + (quad & 1) * 16;
                uint32_t ah[2][4], al[2][4], bh[4][4], bl[4][4];
                #pragma unroll
                for (int mt = 0; mt < 2; mt++) {
                    uint32_t ra = (uint32_t)((warpM * 32 + mt * 16 + (quad & 1) * 8 + r8) * RS) + kbA;
                    ldsm4(ah[mt], pAh + ra);
                    ldsm4(al[mt], pAl + ra);
                }
                #pragma unroll
                for (int nt16 = 0; nt16 < 4; nt16++) {
                    uint32_t rb = (uint32_t)((warpN * 64 + nt16 * 16 + (quad >> 1) * 8 + r8) * RS) + kbB;
                    ldsm4(bh[nt16], pBh + rb);
                    ldsm4(bl[nt16], pBl + rb);
                }
                #pragma unroll
                for (int mt = 0; mt < 2; mt++)
                    #pragma unroll
                    for (int nt16 = 0; nt16 < 4; nt16++) {
                        mma_bf16(acc[mt][nt16 * 2 + 0], ah[mt], &bl[nt16][0]);
                        mma_bf16(acc[mt][nt16 * 2 + 0], al[mt], &bh[nt16][0]);
                        mma_bf16(acc[mt][nt16 * 2 + 0], ah[mt], &bh[nt16][0]);
                        mma_bf16(acc[mt][nt16 * 2 + 1], ah[mt], &bl[nt16][2]);
                        mma_bf16(acc[mt][nt16 * 2 + 1], al[mt], &bh[nt16][2]);
                        mma_bf16(acc[mt][nt16 * 2 + 1], ah[mt], &bh[nt16][2]);
                    }
            }
        }
        buf ^= 1;
    }

    // ---- epilogue: c0(g,2tg) c1(g,2tg+1) c2(g+8,2tg) c3(g+8,2tg+1) ----
    #pragma unroll
    for (int mt = 0; mt < 2; mt++) {
        int rbase = row0 + warpM * 32 + mt * 16 + g;
        #pragma unroll
        for (int nt = 0; nt < 8; nt++) {
            int col = col0 + warpN * 64 + nt * 8 + tg * 2;
            if (col < N) {
                float2 v0 = make_float2(acc[mt][nt][0], acc[mt][nt][1]);
                float2 v1 = make_float2(acc[mt][nt][2], acc[mt][nt][3]);
                if (EPI == 1) {
                    float b0 = bias[col], b1 = bias[col + 1];
                    v0.x = geluf(v0.x + b0); v0.y = geluf(v0.y + b1);
                    v1.x = geluf(v1.x + b0); v1.y = geluf(v1.y + b1);
                }
                if (EPI == 2) {
                    float b0 = bias[col], b1 = bias[col + 1];
                    float2 r0 = *reinterpret_cast<const float2*>(&resid[(long)rbase * N + col]);
                    float2 r1 = *reinterpret_cast<const float2*>(&resid[(long)(rbase + 8) * N + col]);
                    v0.x += b0 + r0.x; v0.y += b1 + r0.y;
                    v1.x += b0 + r1.x; v1.y += b1 + r1.y;
                }
                *reinterpret_cast<float2*>(&C[(long)rbase * N + col])       = v0;
                *reinterpret_cast<float2*>(&C[(long)(rbase + 8) * N + col]) = v1;
            }
        }
    }
}

// ---------------- depthwise conv (causal fwd + anti-causal bwd) + SiLU --------
__global__ void conv_kernel(const float* __restrict__ zx, const float* __restrict__ cw,
                            const float* __restrict__ cb,
                            float* __restrict__ xf, float* __restrict__ xb) {
    long idx = (long)blockIdx.x * blockDim.x + threadIdx.x;
    if (idx >= (long)BT * CONVDIM) return;
    int c = (int)(idx % CONVDIM);
    long bt = idx / CONVDIM;
    int t = (int)(bt % SEQn);
    int b = (int)(bt / SEQn);
    float w0 = cw[c*4+0], w1 = cw[c*4+1], w2 = cw[c*4+2], w3 = cw[c*4+3];
    float bias = cb[c];
    const float* base = zx + ((long)b * SEQn) * DIP + DINNER + c;
    float af = bias;
    if (t >= 3) af += w0 * base[(long)(t-3) * DIP];
    if (t >= 2) af += w1 * base[(long)(t-2) * DIP];
    if (t >= 1) af += w2 * base[(long)(t-1) * DIP];
    af += w3 * base[(long)t * DIP];
    xf[idx] = siluf(af);
    float ab = bias;
    if (t + 3 < SEQn) ab += w0 * base[(long)(t+3) * DIP];
    if (t + 2 < SEQn) ab += w1 * base[(long)(t+2) * DIP];
    if (t + 1 < SEQn) ab += w2 * base[(long)(t+1) * DIP];
    ab += w3 * base[(long)t * DIP];
    xb[idx] = siluf(ab);
}

// ---------------- dt processing ----------------
__global__ void dt_kernel(const float* __restrict__ zx, const float* __restrict__ dt_bias,
                          const float* __restrict__ A_log,
                          float* __restrict__ dtp, float* __restrict__ dAe) {
    int idx = blockIdx.x * blockDim.x + threadIdx.x;
    if (idx >= BT * NHEADSn) return;
    int h = idx % NHEADSn;
    long row = idx / NHEADSn;
    float d = zx[row * DIP + DINNER + CONVDIM + h] + dt_bias[h];
    float sp = (d > 20.f) ? d : log1pf(expf(d));
    dtp[idx] = sp;
    dAe[idx] = expf(-expf(A_log[h]) * sp);
}

// --------- SSM scan: 256 thr, thread owns (p, 16-state chunk) ----------------
__global__ void scan_kernel(const float* __restrict__ xbcf, const float* __restrict__ xbcb,
                            const float* __restrict__ dtp, const float* __restrict__ dAe,
                            const float* __restrict__ Dp_,
                            float* __restrict__ yf, float* __restrict__ yb) {
    int blk = blockIdx.x;
    int dir = blk / (BSZn * NHEADSn);
    int rem = blk % (BSZn * NHEADSn);
    int b = rem / NHEADSn, hh = rem % NHEADSn;
    const float* xBC = dir ? xbcb : xbcf;
    float* y = dir ? yb : yf;
    int tid = threadIdx.x;
    int p = tid >> 2, q = tid & 3;
    float hst[16];
    #pragma unroll
    for (int n = 0; n < 16; n++) hst[n] = 0.f;
    __shared__ float sB[2][DSTATEn], sC[2][DSTATEn];
    float Dv = Dp_[hh];

    int t = dir ? (SEQn - 1) : 0;
    long row = (long)b * SEQn + t;
    const float* xr = xBC + row * CONVDIM;
    float nB = 0.f, nC = 0.f;
    int ldpos = ((tid & 15) * 4 + ((tid >> 4) & 3));
    if (tid < 64)       nB = xr[DINNER + tid];
    else if (tid < 128) nC = xr[DINNER + tid];
    float nx  = xr[hh * HEADDIMn + p];
    float ndt = dtp[row * NHEADSn + hh];
    float ndA = dAe[row * NHEADSn + hh];

    for (int step = 0; step < SEQn; step++) {
        int buf = step & 1;
        if (tid < 64)       sB[buf][ldpos] = nB;
        else if (tid < 128) sC[buf][ldpos] = nC;
        float cx = nx, cdt = ndt, cdA = ndA;
        long crow = row;
        __syncthreads();
        if (step + 1 < SEQn) {
            int t2 = dir ? (SEQn - 2 - step) : (step + 1);
            row = (long)b * SEQn + t2;
            const float* xr2 = xBC + row * CONVDIM;
            if (tid < 64)       nB = xr2[DINNER + tid];
            else if (tid < 128) nC = xr2[DINNER + tid];
            nx  = xr2[hh * HEADDIMn + p];
            ndt = dtp[row * NHEADSn + hh];
            ndA = dAe[row * NHEADSn + hh];
        }
        float c1 = cdt * cx;
        float yv = (q == 0) ? Dv * cx : 0.f;
        #pragma unroll
        for (int n = 0; n < 16; n++) {
            int pos = n * 4 + q;
            hst[n] = cdA * hst[n] + c1 * sB[buf][pos];
            yv += hst[n] * sC[buf][pos];
        }
        yv += __shfl_xor_sync(0xffffffffu, yv, 1);
        yv += __shfl_xor_sync(0xffffffffu, yv, 2);
        if (q == 0) y[crow * DINNER + hh * HEADDIMn + p] = yv;
    }
}

// ---------------- gate + RMSNorm + sum ----------------
__global__ void gatenorm_kernel(const float* __restrict__ yf, const float* __restrict__ yb,
                                const float* __restrict__ zx, const float* __restrict__ nw,
                                float* __restrict__ ysum) {
    int row = blockIdx.x;
    int tid = threadIdx.x;
    const float* z = zx + (long)row * DIP;
    float gf[6], gb[6], ssf = 0.f, ssb = 0.f;
    #pragma unroll
    for (int i = 0; i < 6; i++) {
        int c = tid + i * 256;
        float s = siluf(z[c]);
        float a = yf[(long)row * DINNER + c] * s;
        float d = yb[(long)row * DINNER + c] * s;
        gf[i] = a; gb[i] = d;
        ssf += a * a; ssb += d * d;
    }
    __shared__ float r1[8], r2[8], bres[2];
    float w1 = warp_sum(ssf), w2 = warp_sum(ssb);
    int lane = tid & 31, wid = tid >> 5;
    if (lane == 0) { r1[wid] = w1; r2[wid] = w2; }
    __syncthreads();
    if (tid == 0) {
        float a = 0.f, c = 0.f;
        #pragma unroll
        for (int i = 0; i < 8; i++) { a += r1[i]; c += r2[i]; }
        bres[0] = a; bres[1] = c;
    }
    __syncthreads();
    float rf = rsqrtf(bres[0] * (1.f / DINNER) + EPSV);
    float rb = rsqrtf(bres[1] * (1.f / DINNER) + EPSV);
    #pragma unroll
    for (int i = 0; i < 6; i++) {
        int c = tid + i * 256;
        ysum[(long)row * DINNER + c] = (gf[i] * rf + gb[i] * rb) * nw[c];
    }
}

// ---------------- launch ----------------
extern "C" void kernel_launch(void* const* d_in, const int* in_sizes, int n_in,
                              void* d_out, int out_size) {
    const float* x        = (const float*)d_in[0];
    const float* in_proj  = (const float*)d_in[1];
    const float* conv_w   = (const float*)d_in[2];
    const float* conv_b   = (const float*)d_in[3];
    const float* dt_bias  = (const float*)d_in[4];
    const float* A_log    = (const float*)d_in[5];
    const float* D_param  = (const float*)d_in[6];
    const float* norm_w   = (const float*)d_in[7];
    const float* out_proj = (const float*)d_in[8];
    const float* ln1_w    = (const float*)d_in[9];
    const float* ln1_b    = (const float*)d_in[10];
    const float* ln2_w    = (const float*)d_in[11];
    const float* ln2_b    = (const float*)d_in[12];
    const float* ff_w1    = (const float*)d_in[13];
    const float* ff_b1    = (const float*)d_in[14];
    const float* ff_w2    = (const float*)d_in[15];
    const float* ff_b2    = (const float*)d_in[16];
    float* out = (float*)d_out;

    float *p_xn, *p_zx, *p_xbcf, *p_xbcb, *p_dtp, *p_dAe, *p_yf, *p_yb, *p_ysum, *p_mi, *p_m, *p_h1;
    cudaGetSymbolAddress((void**)&p_xn,   g_xn);
    cudaGetSymbolAddress((void**)&p_zx,   g_zx);
    cudaGetSymbolAddress((void**)&p_xbcf, g_xbcf);
    cudaGetSymbolAddress((void**)&p_xbcb, g_xbcb);
    cudaGetSymbolAddress((void**)&p_dtp,  g_dtp);
    cudaGetSymbolAddress((void**)&p_dAe,  g_dAe);
    cudaGetSymbolAddress((void**)&p_yf,   g_yf);
    cudaGetSymbolAddress((void**)&p_yb,   g_yb);
    cudaGetSymbolAddress((void**)&p_ysum, g_ysum);
    cudaGetSymbolAddress((void**)&p_mi,   g_mi);
    cudaGetSymbolAddress((void**)&p_m,    g_m);
    cudaGetSymbolAddress((void**)&p_h1,   g_h1);

    cudaFuncSetAttribute(gemm_mma<0>, cudaFuncAttributeMaxDynamicSharedMemorySize, GEMM_SMEM);
    cudaFuncSetAttribute(gemm_mma<1>, cudaFuncAttributeMaxDynamicSharedMemorySize, GEMM_SMEM);
    cudaFuncSetAttribute(gemm_mma<2>, cudaFuncAttributeMaxDynamicSharedMemorySize, GEMM_SMEM);

    // 1. ln1(x) -> xn
    ln_kernel<<<BT, 256>>>(x, ln1_w, ln1_b, p_xn);
    // 2. zxbcdt = xn @ in_proj^T   [1024, 3224]
    gemm_mma<0><<<dim3((DIP + 127) / 128, BT / 128), 256, GEMM_SMEM>>>(p_xn, in_proj, nullptr, nullptr, p_zx, BT, DIP, DMODEL);
    // 3. conv + silu (both directions)
    {
        long tot = (long)BT * CONVDIM;
        conv_kernel<<<(int)((tot + 255) / 256), 256>>>(p_zx, conv_w, conv_b, p_xbcf, p_xbcb);
    }
    // 4. dt processing
    dt_kernel<<<(BT * NHEADSn + 255) / 256, 256>>>(p_zx, dt_bias, A_log, p_dtp, p_dAe);
    // 5. SSM scan (both directions)
    scan_kernel<<<2 * BSZn * NHEADSn, 256>>>(p_xbcf, p_xbcb, p_dtp, p_dAe, D_param, p_yf, p_yb);
    // 6. gate + RMSNorm per dir + sum
    gatenorm_kernel<<<BT, 256>>>(p_yf, p_yb, p_zx, norm_w, p_ysum);
    // 7. out_f + out_b = ysum @ out_proj^T  [1024, 768]
    gemm_mma<0><<<dim3(DMODEL / 128, BT / 128), 256, GEMM_SMEM>>>(p_ysum, out_proj, nullptr, nullptr, p_mi, BT, DMODEL, DINNER);
    // 8. ln2
    ln_kernel<<<BT, 256>>>(p_mi, ln2_w, ln2_b, p_m);
    // 9. h1 = gelu(m @ ff_w1^T + b1)  [1024, 3072]
    gemm_mma<1><<<dim3(DFF / 128, BT / 128), 256, GEMM_SMEM>>>(p_m, ff_w1, ff_b1, nullptr, p_h1, BT, DFF, DMODEL);
    // 10. out = h1 @ ff_w2^T + b2 + x
    gemm_mma<2><<<dim3(DMODEL / 128, BT / 128), 256, GEMM_SMEM>>>(p_h1, ff_w2, ff_b2, x, out, BT, DMODEL, DFF);
}

// round 7
// speedup vs baseline: 1.4279x; 1.4279x over previous
#include <cuda_runtime.h>
#include <cuda_bf16.h>
#include <math.h>
#include <stdint.h>

#define BSZn   2
#define SEQn   512
#define DMODEL 768
#define DINNER 1536
#define NHEADSn 24
#define HEADDIMn 64
#define DSTATEn 64
#define CONVDIM 1664
#define DIP    3224
#define BT     (BSZn*SEQn)   // 1024
#define DFF    3072
#define EPSV   1e-5f

typedef __nv_bfloat16 bf16;

// ---------------- scratch ----------------
__device__ float g_zx  [BT*DIP];
__device__ float g_xbcf[BT*CONVDIM];
__device__ float g_xbcb[BT*CONVDIM];
__device__ float g_dtp [BT*NHEADSn];
__device__ float g_dAe [BT*NHEADSn];
__device__ float g_yf  [BT*DINNER];
__device__ float g_yb  [BT*DINNER];
__device__ float g_mi  [BT*DMODEL];
// bf16 hi/lo activation planes
__device__ __align__(16) bf16 g_xnh [BT*DMODEL],  g_xnl [BT*DMODEL];
__device__ __align__(16) bf16 g_ysh [BT*DINNER],  g_ysl [BT*DINNER];
__device__ __align__(16) bf16 g_mh  [BT*DMODEL],  g_ml  [BT*DMODEL];
__device__ __align__(16) bf16 g_h1h [BT*DFF],     g_h1l [BT*DFF];
// bf16 hi/lo weight planes
__device__ __align__(16) bf16 g_wip_h[DIP*DMODEL],   g_wip_l[DIP*DMODEL];
__device__ __align__(16) bf16 g_wop_h[DMODEL*DINNER], g_wop_l[DMODEL*DINNER];
__device__ __align__(16) bf16 g_w1_h [DFF*DMODEL],   g_w1_l [DFF*DMODEL];
__device__ __align__(16) bf16 g_w2_h [DMODEL*DFF],   g_w2_l [DMODEL*DFF];

// ---------------- helpers ----------------
__device__ __forceinline__ float warp_sum(float v) {
    #pragma unroll
    for (int o = 16; o > 0; o >>= 1) v += __shfl_xor_sync(0xffffffffu, v, o);
    return v;
}
__device__ __forceinline__ float siluf(float x) { return x / (1.f + expf(-x)); }
__device__ __forceinline__ float geluf(float x) { return 0.5f * x * (1.f + erff(x * 0.70710678118654752f)); }

__device__ __forceinline__ uint32_t smem_u32(const void* p) {
    uint32_t a;
    asm("{ .reg .u64 t; cvta.to.shared.u64 t, %1; cvt.u32.u64 %0, t; }" : "=r"(a) : "l"(p));
    return a;
}
__device__ __forceinline__ void mma_bf16(float* c, const uint32_t* a, const uint32_t* b) {
    asm volatile(
        "mma.sync.aligned.m16n8k16.row.col.f32.bf16.bf16.f32 "
        "{%0,%1,%2,%3},{%4,%5,%6,%7},{%8,%9},{%0,%1,%2,%3};"
        : "+f"(c[0]), "+f"(c[1]), "+f"(c[2]), "+f"(c[3])
        : "r"(a[0]), "r"(a[1]), "r"(a[2]), "r"(a[3]), "r"(b[0]), "r"(b[1]));
}
__device__ __forceinline__ void ldsm4(uint32_t* r, uint32_t addr) {
    asm volatile("ldmatrix.sync.aligned.m8n8.x4.shared.b16 {%0,%1,%2,%3}, [%4];"
                 : "=r"(r[0]), "=r"(r[1]), "=r"(r[2]), "=r"(r[3]) : "r"(addr));
}
__device__ __forceinline__ void cpasync16(uint32_t dst, const void* src, uint32_t ssz) {
    asm volatile("cp.async.cg.shared.global [%0], [%1], 16, %2;"
                 :: "r"(dst), "l"(src), "r"(ssz) : "memory");
}
__device__ __forceinline__ void cp_commit() {
    asm volatile("cp.async.commit_group;" ::: "memory");
}
template<int Np>
__device__ __forceinline__ void cp_wait() {
    asm volatile("cp.async.wait_group %0;" :: "n"(Np) : "memory");
}
__device__ __forceinline__ void split1(float x, bf16& h, bf16& l) {
    h = __float2bfloat16_rn(x);
    l = __float2bfloat16_rn(x - __bfloat162float(h));
}

// ---------------- weight hi/lo split ----------------
__global__ void wsplit_kernel(const float* __restrict__ w, bf16* __restrict__ wh,
                              bf16* __restrict__ wl, int n4) {
    int i = blockIdx.x * blockDim.x + threadIdx.x;
    if (i >= n4) return;
    float4 v = reinterpret_cast<const float4*>(w)[i];
    bf16 h0, h1, h2, h3, l0, l1, l2, l3;
    split1(v.x, h0, l0); split1(v.y, h1, l1);
    split1(v.z, h2, l2); split1(v.w, h3, l3);
    __nv_bfloat162 hp0; hp0.x = h0; hp0.y = h1;
    __nv_bfloat162 hp1; hp1.x = h2; hp1.y = h3;
    __nv_bfloat162 lp0; lp0.x = l0; lp0.y = l1;
    __nv_bfloat162 lp1; lp1.x = l2; lp1.y = l3;
    uint2 hh = make_uint2(*reinterpret_cast<uint32_t*>(&hp0), *reinterpret_cast<uint32_t*>(&hp1));
    uint2 ll = make_uint2(*reinterpret_cast<uint32_t*>(&lp0), *reinterpret_cast<uint32_t*>(&lp1));
    reinterpret_cast<uint2*>(wh)[i] = hh;
    reinterpret_cast<uint2*>(wl)[i] = ll;
}

// ---------------- LayerNorm -> bf16 hi/lo planes ----------------
__global__ void ln_hl_kernel(const float* __restrict__ in, const float* __restrict__ w,
                             const float* __restrict__ b,
                             bf16* __restrict__ oh, bf16* __restrict__ ol) {
    int row = blockIdx.x;
    int tid = threadIdx.x;
    const float* x = in + (long)row * DMODEL;
    float v[3], s = 0.f, ss = 0.f;
    #pragma unroll
    for (int i = 0; i < 3; i++) {
        v[i] = x[tid + i * 256];
        s += v[i]; ss += v[i] * v[i];
    }
    __shared__ float sr[8], sr2[8], bres[2];
    float ws = warp_sum(s), ws2 = warp_sum(ss);
    int lane = tid & 31, wid = tid >> 5;
    if (lane == 0) { sr[wid] = ws; sr2[wid] = ws2; }
    __syncthreads();
    if (tid == 0) {
        float a = 0.f, c = 0.f;
        #pragma unroll
        for (int i = 0; i < 8; i++) { a += sr[i]; c += sr2[i]; }
        bres[0] = a; bres[1] = c;
    }
    __syncthreads();
    float mu  = bres[0] * (1.f / DMODEL);
    float var = bres[1] * (1.f / DMODEL) - mu * mu;
    float r = rsqrtf(var + EPSV);
    #pragma unroll
    for (int i = 0; i < 3; i++) {
        int c = tid + i * 256;
        float o = (v[i] - mu) * r * w[c] + b[c];
        bf16 h, l; split1(o, h, l);
        oh[(long)row * DMODEL + c] = h;
        ol[(long)row * DMODEL + c] = l;
    }
}

// ======= GEMM (pre-split bf16 hi/lo, cp.async x3, ldmatrix, HMMA 3-product) ==
// C[M,N] = A[M,K] @ W[N,K]^T. CTA tile 128x64, BK=32, 8 warps (4M x 2N).
// EPI: 0=none, 1=gelu(v+bias), 2=v+bias+resid. OUTHL: 1 -> write Ch/Cl planes.
#define RS 80
#define A_PL (128 * RS)          // 10240
#define B_PL (64 * RS)           // 5120
#define STG  (2 * A_PL + 2 * B_PL) // 30720
#define GEMM_SMEM (3 * STG)      // 92160

template<int EPI, int OUTHL>
__global__ void __launch_bounds__(256, 2) gemm_bf16p(
        const bf16* __restrict__ Ah_, const bf16* __restrict__ Al_,
        const bf16* __restrict__ Wh_, const bf16* __restrict__ Wl_,
        const float* __restrict__ bias, const float* __restrict__ resid,
        float* __restrict__ C, bf16* __restrict__ Ch, bf16* __restrict__ Cl,
        int M, int N, int K) {
    extern __shared__ char smem[];
    uint32_t sb = smem_u32(smem);
    const int tid = threadIdx.x;
    const int lane = tid & 31, wid = tid >> 5;
    const int warpM = wid & 3, warpN = wid >> 2;
    const int row0 = blockIdx.y * 128;
    const int col0 = blockIdx.x * 64;
    const int quad = lane >> 3, r8 = lane & 7;
    const int g = lane >> 2, tg = lane & 3;

    float acc[2][4][4];
    #pragma unroll
    for (int mt = 0; mt < 2; mt++)
        #pragma unroll
        for (int nt = 0; nt < 4; nt++)
            #pragma unroll
            for (int i = 0; i < 4; i++) acc[mt][nt][i] = 0.f;

    // precompute per-thread chunk coords
    const int ar0 = tid >> 2,          ac0 = tid & 3;         // A chunk set 0 (c=tid)
    const int ar1 = (tid + 256) >> 2,  ac1 = ac0;             // A chunk set 1 (c=tid+256)
    const int br  = tid >> 2,          bc  = tid & 3;         // B chunk (c=tid), br 0..63
    const int bn  = col0 + br;
    const int bnc = bn < N ? bn : (N - 1);
    const uint32_t bsz = bn < N ? 16u : 0u;

    auto issue = [&](int kt, int st) {
        uint32_t base = sb + st * STG;
        int k0 = kt * 32;
        cpasync16(base + ar0 * RS + ac0 * 16,        &Ah_[(long)(row0 + ar0) * K + k0 + ac0 * 8], 16);
        cpasync16(base + A_PL + ar0 * RS + ac0 * 16, &Al_[(long)(row0 + ar0) * K + k0 + ac0 * 8], 16);
        cpasync16(base + ar1 * RS + ac1 * 16,        &Ah_[(long)(row0 + ar1) * K + k0 + ac1 * 8], 16);
        cpasync16(base + A_PL + ar1 * RS + ac1 * 16, &Al_[(long)(row0 + ar1) * K + k0 + ac1 * 8], 16);
        cpasync16(base + 2 * A_PL + br * RS + bc * 16,        &Wh_[(long)bnc * K + k0 + bc * 8], bsz);
        cpasync16(base + 2 * A_PL + B_PL + br * RS + bc * 16, &Wl_[(long)bnc * K + k0 + bc * 8], bsz);
        cp_commit();
    };

    const int ntiles = K / 32;
    issue(0, 0);
    issue(1, 1);

    for (int kt = 0; kt < ntiles; kt++) {
        cp_wait<1>();
        __syncthreads();
        if (kt + 2 < ntiles) issue(kt + 2, (kt + 2) % 3);
        else cp_commit();

        uint32_t base = sb + (kt % 3) * STG;
        uint32_t pAh = base, pAl = base + A_PL;
        uint32_t pBh = base + 2 * A_PL, pBl = pBh + B_PL;
        #pragma unroll
        for (int slab = 0; slab < 2; slab++) {
            uint32_t kbA = slab * 32 + (quad >> 1) * 16;
            uint32_t kbB = slab * 32 + (quad & 1) * 16;
            uint32_t ah[2][4], al[2][4], bh[2][4], bl[2][4];
            #pragma unroll
            for (int mt = 0; mt < 2; mt++) {
                uint32_t ra = (uint32_t)((warpM * 32 + mt * 16 + (quad & 1) * 8 + r8) * RS) + kbA;
                ldsm4(ah[mt], pAh + ra);
                ldsm4(al[mt], pAl + ra);
            }
            #pragma unroll
            for (int nt16 = 0; nt16 < 2; nt16++) {
                uint32_t rb = (uint32_t)((warpN * 32 + nt16 * 16 + (quad >> 1) * 8 + r8) * RS) + kbB;
                ldsm4(bh[nt16], pBh + rb);
                ldsm4(bl[nt16], pBl + rb);
            }
            #pragma unroll
            for (int mt = 0; mt < 2; mt++)
                #pragma unroll
                for (int nt16 = 0; nt16 < 2; nt16++) {
                    mma_bf16(acc[mt][nt16 * 2 + 0], ah[mt], &bl[nt16][0]);
                    mma_bf16(acc[mt][nt16 * 2 + 0], al[mt], &bh[nt16][0]);
                    mma_bf16(acc[mt][nt16 * 2 + 0], ah[mt], &bh[nt16][0]);
                    mma_bf16(acc[mt][nt16 * 2 + 1], ah[mt], &bl[nt16][2]);
                    mma_bf16(acc[mt][nt16 * 2 + 1], al[mt], &bh[nt16][2]);
                    mma_bf16(acc[mt][nt16 * 2 + 1], ah[mt], &bh[nt16][2]);
                }
        }
    }

    // epilogue: c0(g,2tg) c1(g,2tg+1) c2(g+8,2tg) c3(g+8,2tg+1)
    #pragma unroll
    for (int mt = 0; mt < 2; mt++) {
        int rbase = row0 + warpM * 32 + mt * 16 + g;
        #pragma unroll
        for (int nt = 0; nt < 4; nt++) {
            int col = col0 + warpN * 32 + nt * 8 + tg * 2;
            if (col < N) {
                float2 v0 = make_float2(acc[mt][nt][0], acc[mt][nt][1]);
                float2 v1 = make_float2(acc[mt][nt][2], acc[mt][nt][3]);
                if (EPI == 1) {
                    float b0 = bias[col], b1 = bias[col + 1];
                    v0.x = geluf(v0.x + b0); v0.y = geluf(v0.y + b1);
                    v1.x = geluf(v1.x + b0); v1.y = geluf(v1.y + b1);
                }
                if (EPI == 2) {
                    float b0 = bias[col], b1 = bias[col + 1];
                    float2 r0 = *reinterpret_cast<const float2*>(&resid[(long)rbase * N + col]);
                    float2 r1 = *reinterpret_cast<const float2*>(&resid[(long)(rbase + 8) * N + col]);
                    v0.x += b0 + r0.x; v0.y += b1 + r0.y;
                    v1.x += b0 + r1.x; v1.y += b1 + r1.y;
                }
                if (OUTHL) {
                    bf16 h0, h1, l0, l1;
                    split1(v0.x, h0, l0); split1(v0.y, h1, l1);
                    __nv_bfloat162 hp; hp.x = h0; hp.y = h1;
                    __nv_bfloat162 lp; lp.x = l0; lp.y = l1;
                    *reinterpret_cast<uint32_t*>(&Ch[(long)rbase * N + col]) = *reinterpret_cast<uint32_t*>(&hp);
                    *reinterpret_cast<uint32_t*>(&Cl[(long)rbase * N + col]) = *reinterpret_cast<uint32_t*>(&lp);
                    split1(v1.x, h0, l0); split1(v1.y, h1, l1);
                    hp.x = h0; hp.y = h1; lp.x = l0; lp.y = l1;
                    *reinterpret_cast<uint32_t*>(&Ch[(long)(rbase + 8) * N + col]) = *reinterpret_cast<uint32_t*>(&hp);
                    *reinterpret_cast<uint32_t*>(&Cl[(long)(rbase + 8) * N + col]) = *reinterpret_cast<uint32_t*>(&lp);
                } else {
                    *reinterpret_cast<float2*>(&C[(long)rbase * N + col])       = v0;
                    *reinterpret_cast<float2*>(&C[(long)(rbase + 8) * N + col]) = v1;
                }
            }
        }
    }
}

// ---------------- depthwise conv (causal fwd + anti-causal bwd) + SiLU --------
__global__ void conv_kernel(const float* __restrict__ zx, const float* __restrict__ cw,
                            const float* __restrict__ cb,
                            float* __restrict__ xf, float* __restrict__ xb) {
    long idx = (long)blockIdx.x * blockDim.x + threadIdx.x;
    if (idx >= (long)BT * CONVDIM) return;
    int c = (int)(idx % CONVDIM);
    long bt = idx / CONVDIM;
    int t = (int)(bt % SEQn);
    int b = (int)(bt / SEQn);
    float w0 = cw[c*4+0], w1 = cw[c*4+1], w2 = cw[c*4+2], w3 = cw[c*4+3];
    float bias = cb[c];
    const float* base = zx + ((long)b * SEQn) * DIP + DINNER + c;
    float af = bias;
    if (t >= 3) af += w0 * base[(long)(t-3) * DIP];
    if (t >= 2) af += w1 * base[(long)(t-2) * DIP];
    if (t >= 1) af += w2 * base[(long)(t-1) * DIP];
    af += w3 * base[(long)t * DIP];
    xf[idx] = siluf(af);
    float ab = bias;
    if (t + 3 < SEQn) ab += w0 * base[(long)(t+3) * DIP];
    if (t + 2 < SEQn) ab += w1 * base[(long)(t+2) * DIP];
    if (t + 1 < SEQn) ab += w2 * base[(long)(t+1) * DIP];
    ab += w3 * base[(long)t * DIP];
    xb[idx] = siluf(ab);
}

// ---------------- dt processing ----------------
__global__ void dt_kernel(const float* __restrict__ zx, const float* __restrict__ dt_bias,
                          const float* __restrict__ A_log,
                          float* __restrict__ dtp, float* __restrict__ dAe) {
    int idx = blockIdx.x * blockDim.x + threadIdx.x;
    if (idx >= BT * NHEADSn) return;
    int h = idx % NHEADSn;
    long row = idx / NHEADSn;
    float d = zx[row * DIP + DINNER + CONVDIM + h] + dt_bias[h];
    float sp = (d > 20.f) ? d : log1pf(expf(d));
    dtp[idx] = sp;
    dAe[idx] = expf(-expf(A_log[h]) * sp);
}

// --------- SSM scan: 256 thr, thread owns (p, 16-state chunk) ----------------
__global__ void scan_kernel(const float* __restrict__ xbcf, const float* __restrict__ xbcb,
                            const float* __restrict__ dtp, const float* __restrict__ dAe,
                            const float* __restrict__ Dp_,
                            float* __restrict__ yf, float* __restrict__ yb) {
    int blk = blockIdx.x;
    int dir = blk / (BSZn * NHEADSn);
    int rem = blk % (BSZn * NHEADSn);
    int b = rem / NHEADSn, hh = rem % NHEADSn;
    const float* xBC = dir ? xbcb : xbcf;
    float* y = dir ? yb : yf;
    int tid = threadIdx.x;
    int p = tid >> 2, q = tid & 3;
    float hst[16];
    #pragma unroll
    for (int n = 0; n < 16; n++) hst[n] = 0.f;
    __shared__ float sB[2][DSTATEn], sC[2][DSTATEn];
    float Dv = Dp_[hh];

    int t = dir ? (SEQn - 1) : 0;
    long row = (long)b * SEQn + t;
    const float* xr = xBC + row * CONVDIM;
    float nB = 0.f, nC = 0.f;
    int ldpos = ((tid & 15) * 4 + ((tid >> 4) & 3));
    if (tid < 64)       nB = xr[DINNER + tid];
    else if (tid < 128) nC = xr[DINNER + tid];
    float nx  = xr[hh * HEADDIMn + p];
    float ndt = dtp[row * NHEADSn + hh];
    float ndA = dAe[row * NHEADSn + hh];

    for (int step = 0; step < SEQn; step++) {
        int buf = step & 1;
        if (tid < 64)       sB[buf][ldpos] = nB;
        else if (tid < 128) sC[buf][ldpos] = nC;
        float cx = nx, cdt = ndt, cdA = ndA;
        long crow = row;
        __syncthreads();
        if (step + 1 < SEQn) {
            int t2 = dir ? (SEQn - 2 - step) : (step + 1);
            row = (long)b * SEQn + t2;
            const float* xr2 = xBC + row * CONVDIM;
            if (tid < 64)       nB = xr2[DINNER + tid];
            else if (tid < 128) nC = xr2[DINNER + tid];
            nx  = xr2[hh * HEADDIMn + p];
            ndt = dtp[row * NHEADSn + hh];
            ndA = dAe[row * NHEADSn + hh];
        }
        float c1 = cdt * cx;
        float yv = (q == 0) ? Dv * cx : 0.f;
        #pragma unroll
        for (int n = 0; n < 16; n++) {
            int pos = n * 4 + q;
            hst[n] = cdA * hst[n] + c1 * sB[buf][pos];
            yv += hst[n] * sC[buf][pos];
        }
        yv += __shfl_xor_sync(0xffffffffu, yv, 1);
        yv += __shfl_xor_sync(0xffffffffu, yv, 2);
        if (q == 0) y[crow * DINNER + hh * HEADDIMn + p] = yv;
    }
}

// ------ gate + RMSNorm + sum -> bf16 hi/lo planes ----------------
__global__ void gatenorm_kernel(const float* __restrict__ yf, const float* __restrict__ yb,
                                const float* __restrict__ zx, const float* __restrict__ nw,
                                bf16* __restrict__ oh, bf16* __restrict__ ol) {
    int row = blockIdx.x;
    int tid = threadIdx.x;
    const float* z = zx + (long)row * DIP;
    float gf[6], gb[6], ssf = 0.f, ssb = 0.f;
    #pragma unroll
    for (int i = 0; i < 6; i++) {
        int c = tid + i * 256;
        float s = siluf(z[c]);
        float a = yf[(long)row * DINNER + c] * s;
        float d = yb[(long)row * DINNER + c] * s;
        gf[i] = a; gb[i] = d;
        ssf += a * a; ssb += d * d;
    }
    __shared__ float r1[8], r2[8], bres[2];
    float w1 = warp_sum(ssf), w2 = warp_sum(ssb);
    int lane = tid & 31, wid = tid >> 5;
    if (lane == 0) { r1[wid] = w1; r2[wid] = w2; }
    __syncthreads();
    if (tid == 0) {
        float a = 0.f, c = 0.f;
        #pragma unroll
        for (int i = 0; i < 8; i++) { a += r1[i]; c += r2[i]; }
        bres[0] = a; bres[1] = c;
    }
    __syncthreads();
    float rf = rsqrtf(bres[0] * (1.f / DINNER) + EPSV);
    float rb = rsqrtf(bres[1] * (1.f / DINNER) + EPSV);
    #pragma unroll
    for (int i = 0; i < 6; i++) {
        int c = tid + i * 256;
        float o = (gf[i] * rf + gb[i] * rb) * nw[c];
        bf16 h, l; split1(o, h, l);
        oh[(long)row * DINNER + c] = h;
        ol[(long)row * DINNER + c] = l;
    }
}

// ---------------- launch ----------------
extern "C" void kernel_launch(void* const* d_in, const int* in_sizes, int n_in,
                              void* d_out, int out_size) {
    const float* x        = (const float*)d_in[0];
    const float* in_proj  = (const float*)d_in[1];
    const float* conv_w   = (const float*)d_in[2];
    const float* conv_b   = (const float*)d_in[3];
    const float* dt_bias  = (const float*)d_in[4];
    const float* A_log    = (const float*)d_in[5];
    const float* D_param  = (const float*)d_in[6];
    const float* norm_w   = (const float*)d_in[7];
    const float* out_proj = (const float*)d_in[8];
    const float* ln1_w    = (const float*)d_in[9];
    const float* ln1_b    = (const float*)d_in[10];
    const float* ln2_w    = (const float*)d_in[11];
    const float* ln2_b    = (const float*)d_in[12];
    const float* ff_w1    = (const float*)d_in[13];
    const float* ff_b1    = (const float*)d_in[14];
    const float* ff_w2    = (const float*)d_in[15];
    const float* ff_b2    = (const float*)d_in[16];
    float* out = (float*)d_out;

    float *p_zx, *p_xbcf, *p_xbcb, *p_dtp, *p_dAe, *p_yf, *p_yb, *p_mi;
    bf16 *p_xnh, *p_xnl, *p_ysh, *p_ysl, *p_mh, *p_ml, *p_h1h, *p_h1l;
    bf16 *p_wip_h, *p_wip_l, *p_wop_h, *p_wop_l, *p_w1_h, *p_w1_l, *p_w2_h, *p_w2_l;
    cudaGetSymbolAddress((void**)&p_zx,   g_zx);
    cudaGetSymbolAddress((void**)&p_xbcf, g_xbcf);
    cudaGetSymbolAddress((void**)&p_xbcb, g_xbcb);
    cudaGetSymbolAddress((void**)&p_dtp,  g_dtp);
    cudaGetSymbolAddress((void**)&p_dAe,  g_dAe);
    cudaGetSymbolAddress((void**)&p_yf,   g_yf);
    cudaGetSymbolAddress((void**)&p_yb,   g_yb);
    cudaGetSymbolAddress((void**)&p_mi,   g_mi);
    cudaGetSymbolAddress((void**)&p_xnh,  g_xnh);
    cudaGetSymbolAddress((void**)&p_xnl,  g_xnl);
    cudaGetSymbolAddress((void**)&p_ysh,  g_ysh);
    cudaGetSymbolAddress((void**)&p_ysl,  g_ysl);
    cudaGetSymbolAddress((void**)&p_mh,   g_mh);
    cudaGetSymbolAddress((void**)&p_ml,   g_ml);
    cudaGetSymbolAddress((void**)&p_h1h,  g_h1h);
    cudaGetSymbolAddress((void**)&p_h1l,  g_h1l);
    cudaGetSymbolAddress((void**)&p_wip_h, g_wip_h);
    cudaGetSymbolAddress((void**)&p_wip_l, g_wip_l);
    cudaGetSymbolAddress((void**)&p_wop_h, g_wop_h);
    cudaGetSymbolAddress((void**)&p_wop_l, g_wop_l);
    cudaGetSymbolAddress((void**)&p_w1_h,  g_w1_h);
    cudaGetSymbolAddress((void**)&p_w1_l,  g_w1_l);
    cudaGetSymbolAddress((void**)&p_w2_h,  g_w2_h);
    cudaGetSymbolAddress((void**)&p_w2_l,  g_w2_l);

    cudaFuncSetAttribute(gemm_bf16p<0,0>, cudaFuncAttributeMaxDynamicSharedMemorySize, GEMM_SMEM);
    cudaFuncSetAttribute(gemm_bf16p<1,1>, cudaFuncAttributeMaxDynamicSharedMemorySize, GEMM_SMEM);
    cudaFuncSetAttribute(gemm_bf16p<2,0>, cudaFuncAttributeMaxDynamicSharedMemorySize, GEMM_SMEM);

    // 0. split weights to bf16 hi/lo
    wsplit_kernel<<<(DIP*DMODEL/4 + 255) / 256, 256>>>(in_proj,  p_wip_h, p_wip_l, DIP*DMODEL/4);
    wsplit_kernel<<<(DMODEL*DINNER/4 + 255) / 256, 256>>>(out_proj, p_wop_h, p_wop_l, DMODEL*DINNER/4);
    wsplit_kernel<<<(DFF*DMODEL/4 + 255) / 256, 256>>>(ff_w1,    p_w1_h,  p_w1_l,  DFF*DMODEL/4);
    wsplit_kernel<<<(DMODEL*DFF/4 + 255) / 256, 256>>>(ff_w2,    p_w2_h,  p_w2_l,  DMODEL*DFF/4);

    // 1. ln1(x) -> xn planes
    ln_hl_kernel<<<BT, 256>>>(x, ln1_w, ln1_b, p_xnh, p_xnl);
    // 2. zxbcdt = xn @ in_proj^T   [1024, 3224]
    gemm_bf16p<0,0><<<dim3((DIP + 63) / 64, BT / 128), 256, GEMM_SMEM>>>(
        p_xnh, p_xnl, p_wip_h, p_wip_l, nullptr, nullptr, p_zx, nullptr, nullptr, BT, DIP, DMODEL);
    // 3. conv + silu (both directions)
    {
        long tot = (long)BT * CONVDIM;
        conv_kernel<<<(int)((tot + 255) / 256), 256>>>(p_zx, conv_w, conv_b, p_xbcf, p_xbcb);
    }
    // 4. dt processing
    dt_kernel<<<(BT * NHEADSn + 255) / 256, 256>>>(p_zx, dt_bias, A_log, p_dtp, p_dAe);
    // 5. SSM scan
    scan_kernel<<<2 * BSZn * NHEADSn, 256>>>(p_xbcf, p_xbcb, p_dtp, p_dAe, D_param, p_yf, p_yb);
    // 6. gate + RMSNorm per dir + sum -> ysum planes
    gatenorm_kernel<<<BT, 256>>>(p_yf, p_yb, p_zx, norm_w, p_ysh, p_ysl);
    // 7. mi = ysum @ out_proj^T  [1024, 768]
    gemm_bf16p<0,0><<<dim3(DMODEL / 64, BT / 128), 256, GEMM_SMEM>>>(
        p_ysh, p_ysl, p_wop_h, p_wop_l, nullptr, nullptr, p_mi, nullptr, nullptr, BT, DMODEL, DINNER);
    // 8. ln2 -> m planes
    ln_hl_kernel<<<BT, 256>>>(p_mi, ln2_w, ln2_b, p_mh, p_ml);
    // 9. h1 = gelu(m @ ff_w1^T + b1) -> h1 planes  [1024, 3072]
    gemm_bf16p<1,1><<<dim3(DFF / 64, BT / 128), 256, GEMM_SMEM>>>(
        p_mh, p_ml, p_w1_h, p_w1_l, ff_b1, nullptr, nullptr, p_h1h, p_h1l, BT, DFF, DMODEL);
    // 10. out = h1 @ ff_w2^T + b2 + x
    gemm_bf16p<2,0><<<dim3(DMODEL / 64, BT / 128), 256, GEMM_SMEM>>>(
        p_h1h, p_h1l, p_w2_h, p_w2_l, ff_b2, x, out, nullptr, nullptr, BT, DMODEL, DFF);
}